// round 15
// baseline (speedup 1.0000x reference)
#include <cuda_runtime.h>

#define BATCH 8
#define MDIM 256
#define NDIM 256
#define WID 64
#define MODES 16
#define NLAYERS 4

// ---------------- scratch (static device arrays; no allocations) -------------
__device__ float2 g_t1[BATCH*MDIM*MODES*WID];       // 16.8 MB [b][m][ky][c]
__device__ float2 g_X [512*BATCH*WID];              // 2.1 MB  [p][b][c]
__device__ float2 g_Y [512*BATCH*WID];              // 2.1 MB  [p][b][o]
__device__ float2 g_G [BATCH*MDIM*MODES*WID];       // 16.8 MB [b][m][ky][o]
__device__ float2 g_W [NLAYERS*512*64*64];          // 67 MB   folded W'=W(I+lin_w)
__device__ float2 g_tw[256];                        // e^{2*pi*i*k/256}

__device__ __forceinline__ float2 cmul(float2 t, float2 w) {
    return make_float2(t.x * w.x - t.y * w.y, t.x * w.y + t.y * w.x);
}

// ---------------- twiddle table ----------------------------------------------
__global__ void k_twiddle() {
    int k = threadIdx.x;
    float a = (float)k / 128.0f;
    g_tw[k] = make_float2(cospif(a), sinpif(a));
}

// ---------------- fold residual linear into spectral weights ------------------
__global__ void k_wfold(const float* __restrict__ fw1,
                        const float* __restrict__ fw2,
                        const float* __restrict__ lin_w) {
    int bi = blockIdx.x;
    int p  = bi & 511;
    int l  = bi >> 9;
    __shared__ float2 Wp[64][64];
    __shared__ float  lws[32][64];
    int tid = threadIdx.x;

    const float* fw = (p < 256) ? fw1 : fw2;
    int pq = p & 255;
    size_t base = ((size_t)l * 64 * 64 * 256 + pq) * 2;
    for (int k = tid; k < 4096; k += 256) {
        int i = k >> 6, o = k & 63;
        size_t s = base + (size_t)(i * 64 + o) * 512;
        Wp[i][o] = make_float2(fw[s], fw[s + 1]);
    }

    int i0 = (tid >> 4) * 4;
    int o0 = (tid & 15) * 4;
    float accx[4][4], accy[4][4];
#pragma unroll
    for (int ii = 0; ii < 4; ii++)
#pragma unroll
        for (int oo = 0; oo < 4; oo++) { accx[ii][oo] = 0.f; accy[ii][oo] = 0.f; }

    for (int ch = 0; ch < 2; ch++) {
        __syncthreads();
        for (int k = tid; k < 2048; k += 256)
            lws[k >> 6][k & 63] = lin_w[(size_t)l * 4096 + (ch * 32 + (k >> 6)) * 64 + (k & 63)];
        __syncthreads();
#pragma unroll 8
        for (int jj = 0; jj < 32; jj++) {
            int j = ch * 32 + jj;
            float4 w4 = *(const float4*)&lws[jj][o0];
            float2 a0 = Wp[i0 + 0][j];
            float2 a1 = Wp[i0 + 1][j];
            float2 a2 = Wp[i0 + 2][j];
            float2 a3 = Wp[i0 + 3][j];
            accx[0][0] += a0.x * w4.x; accy[0][0] += a0.y * w4.x;
            accx[0][1] += a0.x * w4.y; accy[0][1] += a0.y * w4.y;
            accx[0][2] += a0.x * w4.z; accy[0][2] += a0.y * w4.z;
            accx[0][3] += a0.x * w4.w; accy[0][3] += a0.y * w4.w;
            accx[1][0] += a1.x * w4.x; accy[1][0] += a1.y * w4.x;
            accx[1][1] += a1.x * w4.y; accy[1][1] += a1.y * w4.y;
            accx[1][2] += a1.x * w4.z; accy[1][2] += a1.y * w4.z;
            accx[1][3] += a1.x * w4.w; accy[1][3] += a1.y * w4.w;
            accx[2][0] += a2.x * w4.x; accy[2][0] += a2.y * w4.x;
            accx[2][1] += a2.x * w4.y; accy[2][1] += a2.y * w4.y;
            accx[2][2] += a2.x * w4.z; accy[2][2] += a2.y * w4.z;
            accx[2][3] += a2.x * w4.w; accy[2][3] += a2.y * w4.w;
            accx[3][0] += a3.x * w4.x; accy[3][0] += a3.y * w4.x;
            accx[3][1] += a3.x * w4.y; accy[3][1] += a3.y * w4.y;
            accx[3][2] += a3.x * w4.z; accy[3][2] += a3.y * w4.z;
            accx[3][3] += a3.x * w4.w; accy[3][3] += a3.y * w4.w;
        }
    }
    float2* wout = g_W + (size_t)bi * 4096;
#pragma unroll
    for (int ii = 0; ii < 4; ii++)
#pragma unroll
        for (int oo = 0; oo < 4; oo++) {
            float2 idv = Wp[i0 + ii][o0 + oo];
            wout[(i0 + ii) * 64 + o0 + oo] =
                make_float2(idv.x + accx[ii][oo], idv.y + accy[ii][oo]);
        }
}

// ---------------- f1 DFT phase from smem E/O (shared by pf1/i2f1) ------------
__device__ __forceinline__ void f1_phase(const float(*Es)[64], const float(*Os)[64],
                                         const float2* tw, int bm, int tid) {
    int ky = tid >> 4, cg = tid & 15;
    const float(*src)[64] = (ky & 1) ? Os : Es;
    float ar[4] = {0.f, 0.f, 0.f, 0.f}, ai[4] = {0.f, 0.f, 0.f, 0.f};
    float2 wst = tw[ky];
    for (int nb = 0; nb < 8; nb++) {
        float2 t = tw[(ky * nb * 16) & 255];       // exact resync
#pragma unroll
        for (int ni = 0; ni < 16; ni++) {
            int nn = nb * 16 + ni;
            float4 hv = *(const float4*)&src[nn][cg * 4];
            ar[0] += hv.x * t.x; ai[0] -= hv.x * t.y;
            ar[1] += hv.y * t.x; ai[1] -= hv.y * t.y;
            ar[2] += hv.z * t.x; ai[2] -= hv.z * t.y;
            ar[3] += hv.w * t.x; ai[3] -= hv.w * t.y;
            t = cmul(t, wst);
        }
    }
    float4* op = (float4*)(g_t1 + (size_t)bm * MODES * WID + ky * 64 + cg * 4);
    op[0] = make_float4(ar[0], ai[0], ar[1], ai[1]);
    op[1] = make_float4(ar[2], ai[2], ar[3], ai[3]);
}

// ---------------- pf1: input projection + layer-0 forward DFT (fused) ---------
// block = (b,m): 2048 x 256. dynamic smem: Es/Os 64KB + xs 3KB + w 1.5KB.
__global__ void k_pf1(const float* __restrict__ x,
                      const float* __restrict__ in_w,
                      const float* __restrict__ in_b) {
    extern __shared__ __align__(16) float sm[];
    float(*Es)[64] = (float(*)[64])sm;             // [128][64]
    float(*Os)[64] = (float(*)[64])(sm + 8192);    // [128][64]
    float* xs  = sm + 16384;                        // [768]
    float* ws  = sm + 17152;                        // [5][64]
    float* ib  = sm + 17472;                        // [64]
    __shared__ float2 tw[256];
    int bm = blockIdx.x;
    int m  = bm & 255;
    int tid = threadIdx.x;
    tw[tid] = g_tw[tid];
    const float* xrow = x + (size_t)bm * 768;
    for (int k = tid; k < 768; k += 256) xs[k] = xrow[k];
    for (int k = tid; k < 320; k += 256) ws[k] = in_w[k];   // FIXED: full 320 loads
    if (tid < 64)  ib[tid] = in_b[tid];
    __syncthreads();

    float pm = -1.0f + ((float)m + 0.5f) * (1.0f / 128.0f);
    int tx = tid & 15, ty = tid >> 4;
    int c0 = tx * 4;
#pragma unroll
    for (int k = 0; k < 8; k++) {
        int n = ty * 8 + k;
        int n2 = n + 128;
        float x0 = xs[n * 3], x1 = xs[n * 3 + 1], x2 = xs[n * 3 + 2];
        float y0 = xs[n2 * 3], y1 = xs[n2 * 3 + 1], y2 = xs[n2 * 3 + 2];
        float pn  = -1.0f + ((float)n  + 0.5f) * (1.0f / 128.0f);
        float pn2 = -1.0f + ((float)n2 + 0.5f) * (1.0f / 128.0f);
        float4 e, o;
#pragma unroll
        for (int q = 0; q < 4; q++) {
            int c = c0 + q;
            float base = ib[c] + pm * ws[3 * 64 + c];
            float h0 = base + x0 * ws[c] + x1 * ws[64 + c] + x2 * ws[128 + c]
                            + pn  * ws[4 * 64 + c];
            float h1 = base + y0 * ws[c] + y1 * ws[64 + c] + y2 * ws[128 + c]
                            + pn2 * ws[4 * 64 + c];
            ((float*)&e)[q] = h0 + h1;
            ((float*)&o)[q] = h0 - h1;
        }
        *(float4*)&Es[n][c0] = e;
        *(float4*)&Os[n][c0] = o;
    }
    __syncthreads();
    f1_phase(Es, Os, tw, bm, tid);
}

// ---------------- forward DFT along m (T1 -> X) -------------------------------
__global__ void k_f2() {
    int bi = blockIdx.x;
    int cchunk = bi & 7;
    int ky     = (bi >> 3) & 15;
    int b      = bi >> 7;
    __shared__ float2 tw[256];
    __shared__ float2 Es[64][8];
    __shared__ float2 Os[64][8];
    int tid = threadIdx.x;
    tw[tid] = g_tw[tid];
    int j = tid >> 3, cl = tid & 7;
    int c0 = cchunk * 8;
    int kx = (j < 16) ? j : (224 + j);
    const float2(*src)[8] = (j & 1) ? Os : Es;
    float ar = 0.f, ai = 0.f;
    for (int ch = 0; ch < 2; ch++) {
        int m0 = ch * 64;
        __syncthreads();
#pragma unroll
        for (int i = 0; i < 2; i++) {
            int k = tid + i * 256;
            int m = k >> 3, cc = k & 7;
            float2 a = g_t1[((size_t)((b * 256 + m0 + m) * 16 + ky)) * 64 + c0 + cc];
            float2 d = g_t1[((size_t)((b * 256 + m0 + 128 + m) * 16 + ky)) * 64 + c0 + cc];
            Es[m][cc] = make_float2(a.x + d.x, a.y + d.y);
            Os[m][cc] = make_float2(a.x - d.x, a.y - d.y);
        }
        __syncthreads();
        float2 wst = tw[kx & 255];
        for (int mb = 0; mb < 4; mb++) {
            float2 w = tw[(kx * (m0 + mb * 16)) & 255];
#pragma unroll
            for (int mi = 0; mi < 16; mi++) {
                int mm = mb * 16 + mi;
                float2 t = src[mm][cl];
                ar += t.x * w.x + t.y * w.y;
                ai += t.y * w.x - t.x * w.y;
                w = cmul(w, wst);
            }
        }
    }
    int p = (j < 16) ? (j * 16 + ky) : (256 + (j - 16) * 16 + ky);
    g_X[((size_t)p * 8 + b) * WID + c0 + cl] = make_float2(ar, ai);
}

// ---------------- spectral mixing (X -> Y) ------------------------------------
__global__ void k_mix(int layer) {
    int p = blockIdx.x;
    __shared__ float2 W[64][64];
    __shared__ float  Xr[64][8];
    __shared__ float  Xi[64][8];
    __shared__ float  redr[2][512];
    __shared__ float  redi[2][512];
    int tid = threadIdx.x;
    const float2* wp = g_W + ((size_t)layer * 512 + p) * 4096;
    for (int k = tid; k < 4096; k += 256)
        W[k >> 6][k & 63] = wp[k];
    for (int k = tid; k < 512; k += 256) {
        float2 v = g_X[(size_t)p * 512 + k];
        Xr[k & 63][k >> 6] = v.x;
        Xi[k & 63][k >> 6] = v.y;
    }
    __syncthreads();
    int o = tid & 63, bh = (tid >> 6) & 1, p2 = tid >> 7;
    float ar[4] = {0.f, 0.f, 0.f, 0.f}, ai_[4] = {0.f, 0.f, 0.f, 0.f};
#pragma unroll 8
    for (int ii = 0; ii < 32; ii++) {
        int i = p2 * 32 + ii;
        float2 wv = W[i][o];
        float4 xr = *(const float4*)&Xr[i][bh * 4];
        float4 xi = *(const float4*)&Xi[i][bh * 4];
        ar[0] += xr.x * wv.x - xi.x * wv.y;  ai_[0] += xr.x * wv.y + xi.x * wv.x;
        ar[1] += xr.y * wv.x - xi.y * wv.y;  ai_[1] += xr.y * wv.y + xi.y * wv.x;
        ar[2] += xr.z * wv.x - xi.z * wv.y;  ai_[2] += xr.z * wv.y + xi.z * wv.x;
        ar[3] += xr.w * wv.x - xi.w * wv.y;  ai_[3] += xr.w * wv.y + xi.w * wv.x;
    }
#pragma unroll
    for (int bb = 0; bb < 4; bb++) {
        redr[p2][(bh * 4 + bb) * 64 + o] = ar[bb];
        redi[p2][(bh * 4 + bb) * 64 + o] = ai_[bb];
    }
    __syncthreads();
    for (int k = tid; k < 512; k += 256) {
        g_Y[(size_t)p * 512 + k] =
            make_float2(redr[0][k] + redr[1][k], redi[0][k] + redi[1][k]);
    }
}

// ---------------- inverse DFT along kx (Y -> G) -------------------------------
__global__ void k_i1() {
    int bi = blockIdx.x;
    int quad = bi & 3;
    int ky   = (bi >> 2) & 15;
    int b    = bi >> 6;
    __shared__ float2 tw[256];
    __shared__ float2 Ys[32][64];
    int tid = threadIdx.x;
    tw[tid] = g_tw[tid];
    for (int k = tid; k < 2048; k += 256) {
        int j = k >> 6, o = k & 63;
        int half = j >> 4, jl = j & 15;
        int p = half * 256 + jl * 16 + ky;
        Ys[j][o] = g_Y[((size_t)p * 8 + b) * 64 + o];
    }
    __syncthreads();
    int o = tid & 63, msub = tid >> 6;
    for (int it = 0; it < 8; it++) {
        int m = quad * 32 + it * 4 + msub;
        float2 step = tw[(2 * m) & 255];
        float Er = 0.f, Ei = 0.f, Or = 0.f, Oi = 0.f;
        float2 t = make_float2(1.f, 0.f);
#pragma unroll
        for (int jj = 0; jj < 8; jj++) {
            float2 v = Ys[2 * jj][o];
            Er += v.x * t.x - v.y * t.y;
            Ei += v.x * t.y + v.y * t.x;
            t = cmul(t, step);
        }
        t = tw[(240 * m) & 255];
#pragma unroll
        for (int jj = 8; jj < 16; jj++) {
            float2 v = Ys[2 * jj][o];
            Er += v.x * t.x - v.y * t.y;
            Ei += v.x * t.y + v.y * t.x;
            t = cmul(t, step);
        }
        t = tw[m & 255];
#pragma unroll
        for (int jj = 0; jj < 8; jj++) {
            float2 v = Ys[2 * jj + 1][o];
            Or += v.x * t.x - v.y * t.y;
            Oi += v.x * t.y + v.y * t.x;
            t = cmul(t, step);
        }
        t = tw[(241 * m) & 255];
#pragma unroll
        for (int jj = 8; jj < 16; jj++) {
            float2 v = Ys[2 * jj + 1][o];
            Or += v.x * t.x - v.y * t.y;
            Oi += v.x * t.y + v.y * t.x;
            t = cmul(t, step);
        }
        g_G[(((size_t)b * 256 + m) * 16 + ky) * 64 + o] =
            make_float2(Er + Or, Ei + Oi);
        g_G[(((size_t)b * 256 + m + 128) * 16 + ky) * 64 + o] =
            make_float2(Er - Or, Ei - Oi);
    }
}

// ---------------- i2 phase: G -> relu'd h pairs (r0 = row n, r1 = row n+128) --
__device__ __forceinline__ void i2_rows(const float2(*Gs)[64], const float2* tw,
                                        const float* lb, int n, int c0,
                                        float4& r0, float4& r1) {
    float lb0 = lb[c0], lb1 = lb[c0 + 1], lb2 = lb[c0 + 2], lb3 = lb[c0 + 3];
    float E0 = 0.f, E1 = 0.f, E2 = 0.f, E3 = 0.f;
    float O0 = 0.f, O1 = 0.f, O2 = 0.f, O3 = 0.f;
#pragma unroll
    for (int ky = 0; ky < 16; ky += 2) {
        float2 te = tw[(ky * n) & 255];
        float4 ae = *(const float4*)&Gs[ky][c0];
        float4 be = *(const float4*)&Gs[ky][c0 + 2];
        E0 += ae.x * te.x - ae.y * te.y;
        E1 += ae.z * te.x - ae.w * te.y;
        E2 += be.x * te.x - be.y * te.y;
        E3 += be.z * te.x - be.w * te.y;
        float2 to = tw[((ky + 1) * n) & 255];
        float4 ao = *(const float4*)&Gs[ky + 1][c0];
        float4 bo = *(const float4*)&Gs[ky + 1][c0 + 2];
        O0 += ao.x * to.x - ao.y * to.y;
        O1 += ao.z * to.x - ao.w * to.y;
        O2 += bo.x * to.x - bo.y * to.y;
        O3 += bo.z * to.x - bo.w * to.y;
    }
    r0.x = fmaxf(E0 + O0 + lb0, 0.f);
    r0.y = fmaxf(E1 + O1 + lb1, 0.f);
    r0.z = fmaxf(E2 + O2 + lb2, 0.f);
    r0.w = fmaxf(E3 + O3 + lb3, 0.f);
    r1.x = fmaxf(E0 - O0 + lb0, 0.f);
    r1.y = fmaxf(E1 - O1 + lb1, 0.f);
    r1.z = fmaxf(E2 - O2 + lb2, 0.f);
    r1.w = fmaxf(E3 - O3 + lb3, 0.f);
}

// ---------------- i2f1: inverse-n DFT + relu + next-layer forward-n DFT -------
// block = (b,m): 2048 x 256. dynamic: Es/Os 64KB + Gs 8KB + lb.
__global__ void k_i2f1(const float* __restrict__ lin_b, int layer) {
    extern __shared__ __align__(16) float sm[];
    float(*Es)[64] = (float(*)[64])sm;                 // [128][64]
    float(*Os)[64] = (float(*)[64])(sm + 8192);        // [128][64]
    float2(*Gs)[64] = (float2(*)[64])(sm + 16384);     // [16][64] float2
    float* lb = sm + 18432;                             // [64]
    __shared__ float2 tw[256];
    int bm = blockIdx.x;
    int tid = threadIdx.x;
    tw[tid] = g_tw[tid];
    for (int k = tid; k < 1024; k += 256) {
        int ky = k >> 6, o = k & 63;
        float s = (ky == 0 ? 1.0f : 2.0f) * (1.0f / 65536.0f);
        float2 v = g_G[(size_t)bm * 1024 + k];
        Gs[ky][o] = make_float2(v.x * s, v.y * s);
    }
    if (tid < 64) lb[tid] = lin_b[layer * 64 + tid];
    __syncthreads();
    int tx = tid & 15, ty = tid >> 4;
    int c0 = tx * 4;
#pragma unroll
    for (int k = 0; k < 8; k++) {
        int n = ty * 8 + k;
        float4 r0, r1;
        i2_rows(Gs, tw, lb, n, c0, r0, r1);
        float4 e, o;
        e.x = r0.x + r1.x; e.y = r0.y + r1.y; e.z = r0.z + r1.z; e.w = r0.w + r1.w;
        o.x = r0.x - r1.x; o.y = r0.y - r1.y; o.z = r0.z - r1.z; o.w = r0.w - r1.w;
        *(float4*)&Es[n][c0] = e;
        *(float4*)&Os[n][c0] = o;
    }
    __syncthreads();
    f1_phase(Es, Os, tw, bm, tid);
}

// ---------------- i2out: layer-3 inverse DFT + relu + output head -------------
// block = (b,m): 2048 x 256. dynamic: hs 64KB + Gs 8KB + w1s 32KB + misc.
__global__ void k_i2out(const float* __restrict__ lin_b,
                        const float* __restrict__ out1_w,
                        const float* __restrict__ out1_b,
                        const float* __restrict__ out2_w,
                        const float* __restrict__ out2_b,
                        float* __restrict__ out) {
    extern __shared__ __align__(16) float sm[];
    float(*hs)[64]  = (float(*)[64])sm;                // [256][64]
    float2(*Gs)[64] = (float2(*)[64])(sm + 16384);     // [16][64]
    float(*w1s)[128] = (float(*)[128])(sm + 18432);    // [64][128]
    float* lb  = sm + 26624;                            // [64]
    float* b1s = sm + 26688;                            // [128]
    float* w2s = sm + 26816;                            // [128]
    __shared__ float2 tw[256];
    int bm = blockIdx.x;
    int tid = threadIdx.x;
    tw[tid] = g_tw[tid];
    for (int k = tid; k < 1024; k += 256) {
        int ky = k >> 6, o = k & 63;
        float s = (ky == 0 ? 1.0f : 2.0f) * (1.0f / 65536.0f);
        float2 v = g_G[(size_t)bm * 1024 + k];
        Gs[ky][o] = make_float2(v.x * s, v.y * s);
    }
    for (int k = tid; k < 8192; k += 256) w1s[k >> 7][k & 127] = out1_w[k];
    if (tid < 64)  lb[tid] = lin_b[3 * 64 + tid];
    if (tid < 128) { b1s[tid] = out1_b[tid]; w2s[tid] = out2_w[tid]; }
    float b2 = out2_b[0];
    __syncthreads();
    {
        int tx = tid & 15, ty = tid >> 4;
        int c0 = tx * 4;
#pragma unroll
        for (int k = 0; k < 8; k++) {
            int n = ty * 8 + k;
            float4 r0, r1;
            i2_rows(Gs, tw, lb, n, c0, r0, r1);
            *(float4*)&hs[n][c0] = r0;
            *(float4*)&hs[n + 128][c0] = r1;
        }
    }
    __syncthreads();
    float* op = out + (size_t)bm * NDIM;
    int tx = tid & 31, ty = tid >> 5;
    for (int rnd = 0; rnd < 8; rnd++) {
        float acc[4][4];
#pragma unroll
        for (int k = 0; k < 4; k++)
#pragma unroll
            for (int q = 0; q < 4; q++) acc[k][q] = b1s[tx * 4 + q];
#pragma unroll
        for (int j = 0; j < 64; j++) {
            float4 w4 = *(const float4*)&w1s[j][tx * 4];
#pragma unroll
            for (int k = 0; k < 4; k++) {
                float hv = hs[rnd * 32 + ty * 4 + k][j];
                acc[k][0] += hv * w4.x;
                acc[k][1] += hv * w4.y;
                acc[k][2] += hv * w4.z;
                acc[k][3] += hv * w4.w;
            }
        }
#pragma unroll
        for (int k = 0; k < 4; k++) {
            float part = fmaxf(acc[k][0], 0.f) * w2s[tx * 4 + 0]
                       + fmaxf(acc[k][1], 0.f) * w2s[tx * 4 + 1]
                       + fmaxf(acc[k][2], 0.f) * w2s[tx * 4 + 2]
                       + fmaxf(acc[k][3], 0.f) * w2s[tx * 4 + 3];
#pragma unroll
            for (int off = 16; off > 0; off >>= 1)
                part += __shfl_xor_sync(0xffffffffu, part, off);
            if (tx == 0) op[rnd * 32 + ty * 4 + k] = part + b2;
        }
    }
}

#define PF1_BYTES   ((17472 + 64) * 4)
#define I2F1_BYTES  ((18432 + 64) * 4)
#define I2OUT_BYTES ((26944) * 4)

// ---------------- launch ------------------------------------------------------
extern "C" void kernel_launch(void* const* d_in, const int* in_sizes, int n_in,
                              void* d_out, int out_size) {
    const float* x      = (const float*)d_in[0];
    const float* in_w   = (const float*)d_in[1];
    const float* in_b   = (const float*)d_in[2];
    const float* fw1    = (const float*)d_in[3];
    const float* fw2    = (const float*)d_in[4];
    const float* lin_w  = (const float*)d_in[5];
    const float* lin_b  = (const float*)d_in[6];
    const float* out1_w = (const float*)d_in[7];
    const float* out1_b = (const float*)d_in[8];
    const float* out2_w = (const float*)d_in[9];
    const float* out2_b = (const float*)d_in[10];
    float* out = (float*)d_out;

    cudaFuncSetAttribute(k_pf1,   cudaFuncAttributeMaxDynamicSharedMemorySize, PF1_BYTES);
    cudaFuncSetAttribute(k_i2f1,  cudaFuncAttributeMaxDynamicSharedMemorySize, I2F1_BYTES);
    cudaFuncSetAttribute(k_i2out, cudaFuncAttributeMaxDynamicSharedMemorySize, I2OUT_BYTES);

    k_twiddle<<<1, 256>>>();
    k_wfold<<<NLAYERS * 512, 256>>>(fw1, fw2, lin_w);
    k_pf1<<<BATCH * MDIM, 256, PF1_BYTES>>>(x, in_w, in_b);
    for (int l = 0; l < NLAYERS; l++) {
        k_f2 <<<BATCH * MODES * 8, 256>>>();
        k_mix<<<512, 256>>>(l);
        k_i1 <<<BATCH * MODES * 4, 256>>>();
        if (l < 3) k_i2f1<<<BATCH * MDIM, 256, I2F1_BYTES>>>(lin_b, l);
    }
    k_i2out<<<BATCH * MDIM, 256, I2OUT_BYTES>>>(lin_b, out1_w, out1_b,
                                                out2_w, out2_b, out);
}